// round 2
// baseline (speedup 1.0000x reference)
#include <cuda_runtime.h>
#include <math.h>

// Problem constants
#define Bb 8
#define Nn 4096
#define Cc 512
#define Kk 150
#define MROWS (Bb*Nn)            // 32768

// Scratch (device globals — no allocation allowed)
__device__ float g_K[(size_t)Bb*Nn*Kk];        // seg_ft   (8,4096,150)
__device__ float g_V[(size_t)Bb*Nn*Cc];        // v        (8,4096,512)
__device__ float g_S[(size_t)Bb*Nn*Nn];        // scores   (8,4096,4096)
__device__ float g_O[(size_t)Bb*Nn*Cc];        // attn out (8,4096,512)
__device__ float g_Rinv[(size_t)Bb*Nn];        // 1/rowsum

// ---------------------------------------------------------------------------
// Generic tiled SGEMM: C[m,n] = sum_k A[m,k] * B(k,n)   (+ optional epilogues)
//   TRANSB=true : B stored row-major as (Ncols, Kd)  -> B[n*Kd + k]
//   TRANSB=false: B stored row-major as (Kd, Ncols)  -> B[k*Ncols + n]
// A is always row-major (M, Kd), lda = Kd. C row-major (M, Ncols), ldc = Ncols.
// Batched via blockIdx.z with element strides sA/sB/sC.
// Epilogue: v = acc; if bias v += bias[n]; if rowscale v *= rowscale[bz*M+m];
//           if resid v = (*gammaPtr)*v + resid[m*Ncols+n];
// M must be a multiple of 128 (true for all our launches).
// ---------------------------------------------------------------------------
template<bool TRANSB>
__global__ __launch_bounds__(256, 2)
void sgemm_kernel(const float* __restrict__ A, const float* __restrict__ Bm,
                  float* __restrict__ C, int M, int Ncols, int Kd,
                  size_t sA, size_t sB, size_t sC,
                  const float* __restrict__ bias,
                  const float* __restrict__ rowscale,
                  const float* __restrict__ resid,
                  const float* __restrict__ gammaPtr)
{
    __shared__ float As[16][132];
    __shared__ float Bs[16][132];

    const int bz = blockIdx.z;
    A  += (size_t)bz * sA;
    Bm += (size_t)bz * sB;
    C  += (size_t)bz * sC;

    const int m0 = blockIdx.y * 128;
    const int n0 = blockIdx.x * 128;
    const int tid = threadIdx.x;
    const int tx = tid & 15;        // column group (8 cols)
    const int ty = tid >> 4;        // row group    (8 rows)

    float acc[8][8];
#pragma unroll
    for (int i = 0; i < 8; i++)
#pragma unroll
        for (int j = 0; j < 8; j++) acc[i][j] = 0.f;

    for (int k0 = 0; k0 < Kd; k0 += 16) {
        // Load A tile (128 x 16)
#pragma unroll
        for (int i = 0; i < 8; i++) {
            int idx = tid + i * 256;
            int r = idx >> 4, c = idx & 15;
            int gk = k0 + c;
            As[c][r] = (gk < Kd) ? A[(size_t)(m0 + r) * Kd + gk] : 0.f;
        }
        // Load B tile (16 x 128 into Bs[k][n])
        if (TRANSB) {
#pragma unroll
            for (int i = 0; i < 8; i++) {
                int idx = tid + i * 256;
                int n = idx >> 4, c = idx & 15;
                int gn = n0 + n, gk = k0 + c;
                Bs[c][n] = (gn < Ncols && gk < Kd)
                         ? Bm[(size_t)gn * Kd + gk] : 0.f;
            }
        } else {
#pragma unroll
            for (int i = 0; i < 8; i++) {
                int idx = tid + i * 256;
                int c = idx >> 7, n = idx & 127;
                int gk = k0 + c, gn = n0 + n;
                Bs[c][n] = (gk < Kd && gn < Ncols)
                         ? Bm[(size_t)gk * Ncols + gn] : 0.f;
            }
        }
        __syncthreads();

#pragma unroll
        for (int kk = 0; kk < 16; kk++) {
            float ar[8], br[8];
#pragma unroll
            for (int i = 0; i < 8; i++) ar[i] = As[kk][ty * 8 + i];
#pragma unroll
            for (int j = 0; j < 8; j++) br[j] = Bs[kk][tx * 8 + j];
#pragma unroll
            for (int i = 0; i < 8; i++)
#pragma unroll
                for (int j = 0; j < 8; j++)
                    acc[i][j] = fmaf(ar[i], br[j], acc[i][j]);
        }
        __syncthreads();
    }

    const float gm = gammaPtr ? *gammaPtr : 0.f;
#pragma unroll
    for (int i = 0; i < 8; i++) {
        const int m = m0 + ty * 8 + i;
        const float rs = rowscale ? rowscale[(size_t)bz * M + m] : 1.f;
#pragma unroll
        for (int j = 0; j < 8; j++) {
            const int n = n0 + tx * 8 + j;
            if (n < Ncols) {
                float v = acc[i][j];
                if (bias)     v += bias[n];
                if (rowscale) v *= rs;
                if (resid)    v = gm * v + resid[(size_t)m * Ncols + n];
                C[(size_t)m * Ncols + n] = v;
            }
        }
    }
}

// ---------------------------------------------------------------------------
// Row softmax (unnormalized): row length Nn=4096, one block of 256 per row.
// Writes exp(x - max) back in place and 1/sum to rinv[row].
// ---------------------------------------------------------------------------
__global__ __launch_bounds__(256)
void softmax_rows_kernel(float* __restrict__ S, float* __restrict__ rinv)
{
    const size_t row = blockIdx.x;
    float* p = S + row * (size_t)Nn;
    const int tid = threadIdx.x;

    float v[16];
    float mx = -3.4e38f;
#pragma unroll
    for (int i = 0; i < 16; i++) {
        v[i] = p[tid + i * 256];
        mx = fmaxf(mx, v[i]);
    }

    __shared__ float red[256];
    red[tid] = mx;
    __syncthreads();
    for (int s = 128; s > 0; s >>= 1) {
        if (tid < s) red[tid] = fmaxf(red[tid], red[tid + s]);
        __syncthreads();
    }
    mx = red[0];
    __syncthreads();

    float sum = 0.f;
#pragma unroll
    for (int i = 0; i < 16; i++) {
        v[i] = expf(v[i] - mx);
        sum += v[i];
        p[tid + i * 256] = v[i];
    }
    red[tid] = sum;
    __syncthreads();
    for (int s = 128; s > 0; s >>= 1) {
        if (tid < s) red[tid] += red[tid + s];
        __syncthreads();
    }
    if (tid == 0) rinv[row] = 1.f / red[0];
}

// ---------------------------------------------------------------------------
extern "C" void kernel_launch(void* const* d_in, const int* in_sizes, int n_in,
                              void* d_out, int out_size)
{
    (void)in_sizes; (void)n_in; (void)out_size;
    const float* x     = (const float*)d_in[0];
    const float* Wq    = (const float*)d_in[1];
    const float* bq    = (const float*)d_in[2];
    const float* Wk    = (const float*)d_in[3];
    const float* bk    = (const float*)d_in[4];
    const float* Wv    = (const float*)d_in[5];
    const float* bv    = (const float*)d_in[6];
    const float* Wres  = (const float*)d_in[7];
    const float* bres  = (const float*)d_in[8];
    const float* gamma = (const float*)d_in[9];

    float* out     = (float*)d_out;
    float* segmap  = out;                              // (B,N,K)
    float* featmap = out + (size_t)Bb * Nn * Kk;       // (B,N,C)

    float *pK, *pV, *pS, *pO, *pR;
    cudaGetSymbolAddress((void**)&pK, g_K);
    cudaGetSymbolAddress((void**)&pV, g_V);
    cudaGetSymbolAddress((void**)&pS, g_S);
    cudaGetSymbolAddress((void**)&pO, g_O);
    cudaGetSymbolAddress((void**)&pR, g_Rinv);

    const dim3 blk(256);

    // seg_map = x @ Wq^T + bq   (32768 x 150, Kd=512) -> directly into output
    sgemm_kernel<true><<<dim3(2, 256, 1), blk>>>(
        x, Wq, segmap, MROWS, Kk, Cc, 0, 0, 0, bq, nullptr, nullptr, nullptr);

    // seg_ft = x @ Wk^T + bk
    sgemm_kernel<true><<<dim3(2, 256, 1), blk>>>(
        x, Wk, pK, MROWS, Kk, Cc, 0, 0, 0, bk, nullptr, nullptr, nullptr);

    // v = x @ Wv^T + bv   (32768 x 512)
    sgemm_kernel<true><<<dim3(4, 256, 1), blk>>>(
        x, Wv, pV, MROWS, Cc, Cc, 0, 0, 0, bv, nullptr, nullptr, nullptr);

    // S = Q @ K^T per batch  (4096 x 4096, Kd=150)
    sgemm_kernel<true><<<dim3(32, 32, Bb), blk>>>(
        segmap, pK, pS, Nn, Nn, Kk,
        (size_t)Nn * Kk, (size_t)Nn * Kk, (size_t)Nn * Nn,
        nullptr, nullptr, nullptr, nullptr);

    // In-place unnormalized softmax + inverse row sums
    softmax_rows_kernel<<<Bb * Nn, 256>>>(pS, pR);

    // O = (P @ V) * rinv per batch  (4096 x 512, Kd=4096)
    sgemm_kernel<false><<<dim3(4, 32, Bb), blk>>>(
        pS, pV, pO, Nn, Cc, Nn,
        (size_t)Nn * Nn, (size_t)Nn * Cc, (size_t)Nn * Cc,
        nullptr, pR, nullptr, nullptr);

    // feat_map = gamma * (O @ Wres^T + bres) + x
    sgemm_kernel<true><<<dim3(4, 256, 1), blk>>>(
        pO, Wres, featmap, MROWS, Cc, Cc, 0, 0, 0,
        bres, nullptr, x, gamma);
}

// round 6
// speedup vs baseline: 1.7750x; 1.7750x over previous
#include <cuda_runtime.h>
#include <cstdint>
#include <math.h>

#define Bb 8
#define Nn 4096
#define Cc 512
#define Kk 150
#define MROWS (Bb*Nn)

// ---------------- scratch (device globals; no allocation allowed) -----------
__device__ float g_K   [(size_t)Bb*Nn*Kk];   // seg_ft       (8,4096,150)
__device__ float g_Vt  [(size_t)Cc*MROWS];   // v transposed (512, 32768)
__device__ float g_S   [(size_t)Bb*Nn*Nn];   // scores       (8,4096,4096)
__device__ float g_O   [(size_t)Bb*Nn*Cc];   // attn out     (8,4096,512)
__device__ float g_Rinv[(size_t)MROWS];      // 1/rowsum

// ---------------- helpers ----------------------------------------------------
__device__ __forceinline__ uint32_t f2tf(float v) {
    uint32_t u; asm("cvt.rna.tf32.f32 %0, %1;" : "=r"(u) : "f"(v)); return u;
}

__device__ __forceinline__ void mma8(float* c, const uint32_t* a,
                                     uint32_t b0, uint32_t b1) {
    asm volatile(
        "mma.sync.aligned.m16n8k8.row.col.f32.tf32.tf32.f32 "
        "{%0,%1,%2,%3}, {%4,%5,%6,%7}, {%8,%9}, {%0,%1,%2,%3};"
        : "+f"(c[0]), "+f"(c[1]), "+f"(c[2]), "+f"(c[3])
        : "r"(a[0]), "r"(a[1]), "r"(a[2]), "r"(a[3]), "r"(b0), "r"(b1));
}

// Guarded tile load: zero-fills k >= Kd or invalid row; scalar path when the
// row stride is not float4-aligned (lda=150 cases).
__device__ __forceinline__ float4 ldT(const float* __restrict__ P, int ld,
                                      int row, int k, int Kd, bool rowOK,
                                      bool al) {
    float4 v = make_float4(0.f, 0.f, 0.f, 0.f);
    if (!rowOK) return v;
    const float* p = P + (size_t)row * ld;
    if (al && k + 4 <= Kd) return *(const float4*)(p + k);
    if (k     < Kd) v.x = p[k];
    if (k + 1 < Kd) v.y = p[k + 1];
    if (k + 2 < Kd) v.z = p[k + 2];
    if (k + 3 < Kd) v.w = p[k + 3];
    return v;
}

// ---------------------------------------------------------------------------
// mma.sync tf32 GEMM:  C[m,n] = sum_k A[m,k] * B[n,k]
//   A row stride lda, B row stride ldb (B always "TRANSB" view).
//   SPLIT=true: 3xTF32 (hi*hi + hi*lo + lo*hi) ~fp32 accuracy.
// Tile 128x128, BK=32, 8 warps (2m x 4n), warp tile 64x32.
// SMEM per buffer (floats): A_hi[4096] [A_lo 4096] B_hi[4096] [B_lo 4096]
//   frag-order layout: ((frag*4 + ks)*32 + (lane ^ ks))*4 + reg
// Epilogue: stage tile in smem, then fused bias/rowscale/resid/gamma and
// optional transposed store (C[n*transLd + m]).
// ---------------------------------------------------------------------------
template<bool SPLIT>
__global__ void __launch_bounds__(256, 1)
gemm_mma(const float* __restrict__ A, const float* __restrict__ Bm,
         float* __restrict__ C, int M, int Ncols, int Kd, int lda, int ldb,
         size_t sA, size_t sB, size_t sC,
         const float* __restrict__ bias, const float* __restrict__ rowscale,
         const float* __restrict__ resid, const float* __restrict__ gammaPtr,
         long long transLd)
{
    extern __shared__ __align__(16) float smf[];
    const int tid  = threadIdx.x;
    const int wid  = tid >> 5;
    const int lane = tid & 31;
    const int wm   = wid >> 2;      // 0..1
    const int wn   = wid & 3;       // 0..3
    const int bz   = blockIdx.z;
    A  += (size_t)bz * sA;
    Bm += (size_t)bz * sB;
    C  += (size_t)bz * sC;
    const int m0 = blockIdx.y * 128;
    const int n0 = blockIdx.x * 128;
    const bool alA = ((lda & 3) == 0);
    const bool alB = ((ldb & 3) == 0);

    const int BUFSZ = SPLIT ? 16384 : 8192;   // floats per buffer
    const int OFFB  = SPLIT ? 8192  : 4096;   // B_hi offset within buffer

    float acc[4][4][4];
#pragma unroll
    for (int i = 0; i < 4; i++)
#pragma unroll
        for (int j = 0; j < 4; j++)
#pragma unroll
            for (int r = 0; r < 4; r++) acc[i][j][r] = 0.f;

    const int nch = (Kd + 31) >> 5;
    float4 pa[4], pb[4];

    // ---- fetch chunk ch into registers --------------------------------------
    auto FETCH = [&](int ch) {
        const int k0 = ch << 5;
#pragma unroll
        for (int t = 0; t < 4; t++) {
            int idx = t * 256 + tid;
            int r = idx >> 3, q = idx & 7;
            int k = k0 + (q << 2);
            pa[t] = ldT(A, lda, m0 + r, k, Kd, true, alA);
            pb[t] = ldT(Bm, ldb, n0 + r, k, Kd, (n0 + r) < Ncols, alB);
        }
    };

    // ---- store registers into smem buffer (with tf32 convert + split) ------
    auto STORE = [&](int buf) {
        float* base = smf + buf * BUFSZ;
#pragma unroll
        for (int t = 0; t < 4; t++) {
            int idx = t * 256 + tid;
            int r = idx >> 3, q = idx & 7;
            int ks = q >> 1;
            // A element -> frag coords
            {
                int fm = r >> 4, rr = r & 15;
                int regb = (rr >> 3) + ((q & 1) << 1);
                int ln = (rr & 7) << 2;
                float vv[4] = {pa[t].x, pa[t].y, pa[t].z, pa[t].w};
                uint32_t* dst  = (uint32_t*)base;
                uint32_t* dstl = (uint32_t*)(base + 4096);
                int fbase = (fm * 4 + ks) * 32;
#pragma unroll
                for (int j = 0; j < 4; j++) {
                    int u = (ln + j) ^ ks;
                    uint32_t h = f2tf(vv[j]);
                    dst[(fbase + u) * 4 + regb] = h;
                    if (SPLIT)
                        dstl[(fbase + u) * 4 + regb] =
                            f2tf(vv[j] - __uint_as_float(h));
                }
            }
            // B element -> frag coords (n rows)
            {
                int fn = r >> 3, g = r & 7;
                int rslot = ((fn & 1) << 1) + (q & 1);
                int fnp = fn >> 1;
                float vv[4] = {pb[t].x, pb[t].y, pb[t].z, pb[t].w};
                uint32_t* dst  = (uint32_t*)(base + OFFB);
                uint32_t* dstl = (uint32_t*)(base + OFFB + 4096);
                int fbase = (fnp * 4 + ks) * 32;
#pragma unroll
                for (int j = 0; j < 4; j++) {
                    int u = ((g << 2) + j) ^ ks;
                    uint32_t h = f2tf(vv[j]);
                    dst[(fbase + u) * 4 + rslot] = h;
                    if (SPLIT)
                        dstl[(fbase + u) * 4 + rslot] =
                            f2tf(vv[j] - __uint_as_float(h));
                }
            }
        }
    };

    // ---- compute on buffer ---------------------------------------------------
    auto COMPUTE = [&](int buf) {
        const uint32_t* base = (const uint32_t*)(smf + buf * BUFSZ);
#pragma unroll
        for (int ks = 0; ks < 4; ks++) {
            const int lsw = lane ^ ks;
            uint4 ah[4], bh[2], alo[4], blo[2];
#pragma unroll
            for (int i = 0; i < 4; i++) {
                int off = (((wm * 4 + i) * 4 + ks) * 32 + lsw) * 4;
                ah[i] = *(const uint4*)(base + off);
                if (SPLIT) alo[i] = *(const uint4*)(base + 4096 + off);
            }
#pragma unroll
            for (int p = 0; p < 2; p++) {
                int off = (((wn * 2 + p) * 4 + ks) * 32 + lsw) * 4;
                bh[p] = *(const uint4*)(base + OFFB + off);
                if (SPLIT) blo[p] = *(const uint4*)(base + OFFB + 4096 + off);
            }
#pragma unroll
            for (int i = 0; i < 4; i++) {
#pragma unroll
                for (int f = 0; f < 4; f++) {
                    const uint4& B4 = bh[f >> 1];
                    uint32_t b0 = (f & 1) ? B4.z : B4.x;
                    uint32_t b1 = (f & 1) ? B4.w : B4.y;
                    mma8(acc[i][f], (const uint32_t*)&ah[i], b0, b1);
                    if (SPLIT) {
                        const uint4& L4 = blo[f >> 1];
                        uint32_t l0 = (f & 1) ? L4.z : L4.x;
                        uint32_t l1 = (f & 1) ? L4.w : L4.y;
                        mma8(acc[i][f], (const uint32_t*)&ah[i], l0, l1);
                        mma8(acc[i][f], (const uint32_t*)&alo[i], b0, b1);
                    }
                }
            }
        }
    };

    // ---- main loop ------------------------------------------------------------
    FETCH(0);
    STORE(0);
    __syncthreads();
    for (int i = 0; i < nch; i++) {
        bool have = (i + 1) < nch;
        if (have) FETCH(i + 1);
        COMPUTE(i & 1);
        if (have) STORE((i + 1) & 1);
        __syncthreads();
    }

    // ---- epilogue: stage tile in smem (pitch 132), then coalesced write ------
    float* stage = smf;
    const int g4 = lane >> 2, t4 = lane & 3;
#pragma unroll
    for (int i = 0; i < 4; i++) {
#pragma unroll
        for (int f = 0; f < 4; f++) {
            int ml = wm * 64 + i * 16 + g4;
            int nl = wn * 32 + f * 8 + t4 * 2;
            *(float2*)&stage[ml * 132 + nl]       =
                make_float2(acc[i][f][0], acc[i][f][1]);
            *(float2*)&stage[(ml + 8) * 132 + nl] =
                make_float2(acc[i][f][2], acc[i][f][3]);
        }
    }
    __syncthreads();

    const float gm = gammaPtr ? *gammaPtr : 0.f;
#pragma unroll 4
    for (int t = 0; t < 64; t++) {
        int idx = t * 256 + tid;
        int mm, nn;
        if (transLd) { mm = idx & 127; nn = idx >> 7; }
        else         { nn = idx & 127; mm = idx >> 7; }
        int n = n0 + nn, m = m0 + mm;
        if (n < Ncols) {
            float v = stage[mm * 132 + nn];
            if (bias)     v += __ldg(bias + n);
            if (rowscale) v *= rowscale[(size_t)bz * M + m];
            if (resid)    v = gm * v + resid[(size_t)m * Ncols + n];
            if (transLd)  C[(size_t)n * transLd + m] = v;
            else          C[(size_t)m * Ncols + n]   = v;
        }
    }
}

// ---------------------------------------------------------------------------
// Row softmax (unnormalized): exp(x-max) in place, 1/rowsum to rinv.
// ---------------------------------------------------------------------------
__global__ __launch_bounds__(256)
void softmax_rows_kernel(float* __restrict__ S, float* __restrict__ rinv)
{
    const size_t row = blockIdx.x;
    float* p = S + row * (size_t)Nn;
    const int tid = threadIdx.x;

    float v[16];
    float mx = -3.4e38f;
#pragma unroll
    for (int i = 0; i < 16; i++) {
        v[i] = p[tid + i * 256];
        mx = fmaxf(mx, v[i]);
    }
    __shared__ float red[256];
    red[tid] = mx;
    __syncthreads();
    for (int s = 128; s > 0; s >>= 1) {
        if (tid < s) red[tid] = fmaxf(red[tid], red[tid + s]);
        __syncthreads();
    }
    mx = red[0];
    __syncthreads();

    float sum = 0.f;
#pragma unroll
    for (int i = 0; i < 16; i++) {
        v[i] = expf(v[i] - mx);
        sum += v[i];
        p[tid + i * 256] = v[i];
    }
    red[tid] = sum;
    __syncthreads();
    for (int s = 128; s > 0; s >>= 1) {
        if (tid < s) red[tid] += red[tid + s];
        __syncthreads();
    }
    if (tid == 0) rinv[row] = 1.f / red[0];
}

// ---------------------------------------------------------------------------
#define SMEM_SPLIT (2*16384*4)   // 131072 B
#define SMEM_NS    (128*132*4)   // 67584 B (stage dominates 2*8192*4=65536)

extern "C" void kernel_launch(void* const* d_in, const int* in_sizes, int n_in,
                              void* d_out, int out_size)
{
    (void)in_sizes; (void)n_in; (void)out_size;
    const float* x     = (const float*)d_in[0];
    const float* Wq    = (const float*)d_in[1];
    const float* bq    = (const float*)d_in[2];
    const float* Wk    = (const float*)d_in[3];
    const float* bk    = (const float*)d_in[4];
    const float* Wv    = (const float*)d_in[5];
    const float* bv    = (const float*)d_in[6];
    const float* Wres  = (const float*)d_in[7];
    const float* bres  = (const float*)d_in[8];
    const float* gamma = (const float*)d_in[9];

    float* out     = (float*)d_out;
    float* segmap  = out;                          // (B,N,K)
    float* featmap = out + (size_t)Bb * Nn * Kk;   // (B,N,C)

    float *pK, *pVt, *pS, *pO, *pR;
    cudaGetSymbolAddress((void**)&pK,  g_K);
    cudaGetSymbolAddress((void**)&pVt, g_Vt);
    cudaGetSymbolAddress((void**)&pS,  g_S);
    cudaGetSymbolAddress((void**)&pO,  g_O);
    cudaGetSymbolAddress((void**)&pR,  g_Rinv);

    cudaFuncSetAttribute(gemm_mma<true>,
        cudaFuncAttributeMaxDynamicSharedMemorySize, SMEM_SPLIT);
    cudaFuncSetAttribute(gemm_mma<false>,
        cudaFuncAttributeMaxDynamicSharedMemorySize, SMEM_NS);

    // seg_map = x @ Wq^T + bq  (3xTF32 — feeds softmax logits and is an output)
    gemm_mma<true><<<dim3(2, 256, 1), 256, SMEM_SPLIT>>>(
        x, Wq, segmap, MROWS, Kk, Cc, Cc, Cc, 0, 0, 0,
        bq, nullptr, nullptr, nullptr, 0);

    // seg_ft = x @ Wk^T + bk  (3xTF32)
    gemm_mma<true><<<dim3(2, 256, 1), 256, SMEM_SPLIT>>>(
        x, Wk, pK, MROWS, Kk, Cc, Cc, Cc, 0, 0, 0,
        bk, nullptr, nullptr, nullptr, 0);

    // v = x @ Wv^T + bv, stored TRANSPOSED as (C, B*N)
    gemm_mma<false><<<dim3(4, 256, 1), 256, SMEM_NS>>>(
        x, Wv, pVt, MROWS, Cc, Cc, Cc, Cc, 0, 0, 0,
        bv, nullptr, nullptr, nullptr, (long long)MROWS);

    // S = Q @ K^T per batch (3xTF32 — softmax-sensitive; lda/ldb = 150 scalar path)
    gemm_mma<true><<<dim3(32, 32, Bb), 256, SMEM_SPLIT>>>(
        segmap, pK, pS, Nn, Nn, Kk, Kk, Kk,
        (size_t)Nn * Kk, (size_t)Nn * Kk, (size_t)Nn * Nn,
        nullptr, nullptr, nullptr, nullptr, 0);

    // unnormalized softmax + 1/rowsum
    softmax_rows_kernel<<<MROWS, 256>>>(pS, pR);

    // O = (P @ V) * rinv per batch
    gemm_mma<false><<<dim3(4, 32, Bb), 256, SMEM_NS>>>(
        pS, pVt, pO, Nn, Cc, Nn, Nn, MROWS,
        (size_t)Nn * Nn, (size_t)Nn, (size_t)Nn * Cc,
        nullptr, pR, nullptr, nullptr, 0);

    // feat_map = gamma * (O @ Wres^T + bres) + x
    gemm_mma<false><<<dim3(4, 256, 1), 256, SMEM_NS>>>(
        pO, Wres, featmap, MROWS, Cc, Cc, Cc, Cc, 0, 0, 0,
        bres, nullptr, x, gamma, 0);
}

// round 7
// speedup vs baseline: 1.7996x; 1.0139x over previous
#include <cuda_runtime.h>
#include <cstdint>
#include <math.h>

#define Bb 8
#define Nn 4096
#define Cc 512
#define Kk 150
#define MROWS (Bb*Nn)
#define QCW 480          // qcat/kcat row width (3 x 160)

// ---------------- scratch (device globals; no allocation allowed) -----------
__device__ float g_Xcat[(size_t)MROWS*1536]; // [x_hi | x_hi | x_lo]
__device__ float g_Wcat[(size_t)300*1536];   // rows: Wq(150), Wk(150); [hi|lo|hi]
__device__ float g_bqk [512];                // concat(bq, bk)
__device__ float g_Qcat[(size_t)MROWS*QCW];  // [hi|hi|lo], 160-padded blocks
__device__ float g_Kcat[(size_t)MROWS*QCW];  // [hi|lo|hi]
__device__ float g_Vt  [(size_t)Cc*MROWS];   // v transposed (512, 32768)
__device__ float g_S   [(size_t)Bb*Nn*Nn];   // raw scores
__device__ float g_O   [(size_t)Bb*Nn*Cc];   // attn out
__device__ float g_Rmax[(size_t)MROWS];
__device__ float g_Rinv[(size_t)MROWS];

// ---------------- helpers ----------------------------------------------------
__device__ __forceinline__ uint32_t f2tf(float v) {
    uint32_t u; asm("cvt.rna.tf32.f32 %0, %1;" : "=r"(u) : "f"(v)); return u;
}

__device__ __forceinline__ void mma8(float* c, const uint32_t* a,
                                     uint32_t b0, uint32_t b1) {
    asm volatile(
        "mma.sync.aligned.m16n8k8.row.col.f32.tf32.tf32.f32 "
        "{%0,%1,%2,%3}, {%4,%5,%6,%7}, {%8,%9}, {%0,%1,%2,%3};"
        : "+f"(c[0]), "+f"(c[1]), "+f"(c[2]), "+f"(c[3])
        : "r"(a[0]), "r"(a[1]), "r"(a[2]), "r"(a[3]), "r"(b0), "r"(b1));
}

// All launches use float4-aligned strides and Kd % 32 == 0.
__device__ __forceinline__ float4 ld4(const float* __restrict__ P, int ld,
                                      int row, int k, bool rowOK) {
    if (!rowOK) return make_float4(0.f, 0.f, 0.f, 0.f);
    return *(const float4*)(P + (size_t)row * ld + k);
}

// ---------------------------------------------------------------------------
// tf32 mma GEMM:  C[m,n] = sum_k A[m,k] * B[n,k]
// Tile 128x128x32, 8 warps (2m x 4n), warp tile 64x32, double-buffered smem.
// Fragment-order smem: ((frag*4 + ks)*32 + (lane ^ ks))*4 + reg
// Modes:
//   rmaxA != 0 : A elements -> __expf(a - rmax[row])   (PV)
//   qcat  != 0 : QK epilogue (segmap + qcat/kcat hi/lo routing)
//   transLd!=0 : transposed store C[n*transLd + m]
//   else       : +bias[n], *rowscale, gamma*v+resid, row-major store
// ---------------------------------------------------------------------------
__global__ void __launch_bounds__(256, 2)
gemm_mma(const float* __restrict__ A, const float* __restrict__ Bm,
         float* __restrict__ C, int M, int Ncols, int Kd, int lda, int ldb,
         size_t sA, size_t sB, size_t sC,
         const float* __restrict__ bias, const float* __restrict__ rowscale,
         const float* __restrict__ resid, const float* __restrict__ gammaPtr,
         long long transLd,
         const float* __restrict__ rmaxA,
         float* __restrict__ qcat, float* __restrict__ kcat)
{
    extern __shared__ __align__(16) float smf[];
    __shared__ float srmax[128];

    const int tid  = threadIdx.x;
    const int wid  = tid >> 5;
    const int lane = tid & 31;
    const int wm   = wid >> 2;
    const int wn   = wid & 3;
    const int bz   = blockIdx.z;
    A  += (size_t)bz * sA;
    Bm += (size_t)bz * sB;
    C  += (size_t)bz * sC;
    const int m0 = blockIdx.y * 128;
    const int n0 = blockIdx.x * 128;

    const int BUFSZ = 8192;   // floats per buffer
    const int OFFB  = 4096;   // B offset within buffer

    if (rmaxA && tid < 128)
        srmax[tid] = rmaxA[(size_t)bz * M + m0 + tid];

    float acc[4][4][4];
#pragma unroll
    for (int i = 0; i < 4; i++)
#pragma unroll
        for (int j = 0; j < 4; j++)
#pragma unroll
            for (int r = 0; r < 4; r++) acc[i][j][r] = 0.f;

    const int nch = Kd >> 5;
    float4 pa[4], pb[4];

    auto FETCHA = [&](int ch) {
        const int k0 = ch << 5;
#pragma unroll
        for (int t = 0; t < 4; t++) {
            int idx = t * 256 + tid;
            pa[t] = ld4(A, lda, m0 + (idx >> 3), k0 + ((idx & 7) << 2), true);
        }
    };
    auto FETCHB = [&](int ch) {
        const int k0 = ch << 5;
#pragma unroll
        for (int t = 0; t < 4; t++) {
            int idx = t * 256 + tid;
            int r = idx >> 3;
            pb[t] = ld4(Bm, ldb, n0 + r, k0 + ((idx & 7) << 2),
                        (n0 + r) < Ncols);
        }
    };

    auto STOREA = [&](int buf) {
        uint32_t* dst = (uint32_t*)(smf + buf * BUFSZ);
#pragma unroll
        for (int t = 0; t < 4; t++) {
            int idx = t * 256 + tid;
            int r = idx >> 3, q = idx & 7;
            int ks = q >> 1;
            int fm = r >> 4, rr = r & 15;
            int regb = (rr >> 3) + ((q & 1) << 1);
            int ln = (rr & 7) << 2;
            float vv[4] = {pa[t].x, pa[t].y, pa[t].z, pa[t].w};
            if (rmaxA) {
                float mx = srmax[r];
#pragma unroll
                for (int j = 0; j < 4; j++) vv[j] = __expf(vv[j] - mx);
            }
            int fbase = (fm * 4 + ks) * 32;
#pragma unroll
            for (int j = 0; j < 4; j++)
                dst[(fbase + ((ln + j) ^ ks)) * 4 + regb] = f2tf(vv[j]);
        }
    };
    auto STOREB = [&](int buf) {
        uint32_t* dst = (uint32_t*)(smf + buf * BUFSZ + OFFB);
#pragma unroll
        for (int t = 0; t < 4; t++) {
            int idx = t * 256 + tid;
            int r = idx >> 3, q = idx & 7;
            int ks = q >> 1;
            int fn = r >> 3, g = r & 7;
            int rslot = ((fn & 1) << 1) + (q & 1);
            int fnp = fn >> 1;
            float vv[4] = {pb[t].x, pb[t].y, pb[t].z, pb[t].w};
            int fbase = (fnp * 4 + ks) * 32;
#pragma unroll
            for (int j = 0; j < 4; j++)
                dst[(fbase + (((g << 2) + j) ^ ks)) * 4 + rslot] = f2tf(vv[j]);
        }
    };

    auto COMPUTE = [&](int buf, int ks0, int ks1) {
        const uint32_t* base = (const uint32_t*)(smf + buf * BUFSZ);
#pragma unroll
        for (int ks = ks0; ks < ks1; ks++) {
            const int lsw = lane ^ ks;
            uint4 ah[4], bh[2];
#pragma unroll
            for (int i = 0; i < 4; i++)
                ah[i] = *(const uint4*)(base + (((wm * 4 + i) * 4 + ks) * 32 + lsw) * 4);
#pragma unroll
            for (int p = 0; p < 2; p++)
                bh[p] = *(const uint4*)(base + OFFB + (((wn * 2 + p) * 4 + ks) * 32 + lsw) * 4);
#pragma unroll
            for (int i = 0; i < 4; i++)
#pragma unroll
                for (int f = 0; f < 4; f++) {
                    const uint4& B4 = bh[f >> 1];
                    uint32_t b0 = (f & 1) ? B4.z : B4.x;
                    uint32_t b1 = (f & 1) ? B4.w : B4.y;
                    mma8(acc[i][f], (const uint32_t*)&ah[i], b0, b1);
                }
        }
    };

    __syncthreads();                 // srmax visible
    FETCHA(0); STOREA(0);
    FETCHB(0); STOREB(0);
    __syncthreads();
    for (int i = 0; i < nch; i++) {
        bool have = (i + 1) < nch;
        if (have) FETCHA(i + 1);
        COMPUTE(i & 1, 0, 2);
        if (have) { STOREA((i + 1) & 1); FETCHB(i + 1); }
        COMPUTE(i & 1, 2, 4);
        if (have) STOREB((i + 1) & 1);
        __syncthreads();
    }

    // ---- epilogue: stage in smem (pitch 132), then fused coalesced write ----
    float* stage = smf;
    const int g4 = lane >> 2, t4 = lane & 3;
#pragma unroll
    for (int i = 0; i < 4; i++) {
#pragma unroll
        for (int f = 0; f < 4; f++) {
            int ml = wm * 64 + i * 16 + g4;
            int nl = wn * 32 + f * 8 + t4 * 2;
            *(float2*)&stage[ml * 132 + nl]       = make_float2(acc[i][f][0], acc[i][f][1]);
            *(float2*)&stage[(ml + 8) * 132 + nl] = make_float2(acc[i][f][2], acc[i][f][3]);
        }
    }
    __syncthreads();

    if (qcat) {
        // QK epilogue: segmap (fp32) + qcat/kcat hi/lo tf32 routing
#pragma unroll 4
        for (int t = 0; t < 64; t++) {
            int idx = t * 256 + tid;
            int nn = idx & 127, mm = idx >> 7;
            int n = n0 + nn, m = m0 + mm;
            if (n < Ncols) {
                float vb = stage[mm * 132 + nn] + __ldg(bias + n);
                float hi = __uint_as_float(f2tf(vb));
                float lo = __uint_as_float(f2tf(vb - hi));
                if (n < Kk) {
                    C[(size_t)m * Kk + n] = vb;                 // segmap
                    qcat[(size_t)m * QCW + n]       = hi;
                    qcat[(size_t)m * QCW + 160 + n] = hi;
                    qcat[(size_t)m * QCW + 320 + n] = lo;
                } else {
                    int nk = n - Kk;
                    kcat[(size_t)m * QCW + nk]       = hi;
                    kcat[(size_t)m * QCW + 160 + nk] = lo;
                    kcat[(size_t)m * QCW + 320 + nk] = hi;
                }
            }
        }
        return;
    }

    const float gm = gammaPtr ? *gammaPtr : 0.f;
#pragma unroll 4
    for (int t = 0; t < 64; t++) {
        int idx = t * 256 + tid;
        int mm, nn;
        if (transLd) { mm = idx & 127; nn = idx >> 7; }
        else         { nn = idx & 127; mm = idx >> 7; }
        int n = n0 + nn, m = m0 + mm;
        if (n < Ncols) {
            float v = stage[mm * 132 + nn];
            if (bias)     v += __ldg(bias + n);
            if (rowscale) v *= rowscale[(size_t)bz * M + m];
            if (resid)    v = gm * v + resid[(size_t)m * Ncols + n];
            if (transLd)  C[(size_t)n * transLd + m] = v;
            else          C[(size_t)m * Ncols + n]   = v;
        }
    }
}

// ---------------------------------------------------------------------------
// Prep kernels
// ---------------------------------------------------------------------------
__global__ void split_x_kernel(const float* __restrict__ x,
                               float* __restrict__ xcat)
{
    int idx = blockIdx.x * 256 + threadIdx.x;
    if (idx >= MROWS * Cc) return;
    int row = idx >> 9, col = idx & 511;
    float v = x[idx];
    float hi = __uint_as_float(f2tf(v));
    float lo = __uint_as_float(f2tf(v - hi));
    size_t b = (size_t)row * 1536 + col;
    xcat[b] = hi; xcat[b + 512] = hi; xcat[b + 1024] = lo;
}

__global__ void prep_w_kernel(const float* __restrict__ Wq,
                              const float* __restrict__ Wk,
                              const float* __restrict__ bq,
                              const float* __restrict__ bk,
                              float* __restrict__ wcat,
                              float* __restrict__ bqk)
{
    int idx = blockIdx.x * 256 + threadIdx.x;
    if (idx < 300 * 512) {
        int r = idx >> 9, c = idx & 511;
        float v = (r < Kk) ? Wq[r * 512 + c] : Wk[(r - Kk) * 512 + c];
        float hi = __uint_as_float(f2tf(v));
        float lo = __uint_as_float(f2tf(v - hi));
        size_t b = (size_t)r * 1536 + c;
        wcat[b] = hi; wcat[b + 512] = lo; wcat[b + 1024] = hi;
    }
    if (idx < 300) bqk[idx] = (idx < Kk) ? bq[idx] : bk[idx - Kk];
}

__global__ void zero_pads_kernel(float* __restrict__ qcat,
                                 float* __restrict__ kcat)
{
    int row = blockIdx.x;
    int t = threadIdx.x;
    if (t < 30) {
        int col = Kk + (t % 10) + (t / 10) * 160;
        qcat[(size_t)row * QCW + col] = 0.f;
        kcat[(size_t)row * QCW + col] = 0.f;
    }
}

// ---------------------------------------------------------------------------
// Row stats: max and 1/sum(exp(v - max)) per row of S (no write-back).
// ---------------------------------------------------------------------------
__global__ __launch_bounds__(256)
void rowstat_kernel(const float* __restrict__ S,
                    float* __restrict__ rmax, float* __restrict__ rinv)
{
    const size_t row = blockIdx.x;
    const float* p = S + row * (size_t)Nn;
    const int tid = threadIdx.x;

    float v[16];
    float mx = -3.4e38f;
#pragma unroll
    for (int i = 0; i < 16; i++) {
        v[i] = p[tid + i * 256];
        mx = fmaxf(mx, v[i]);
    }
    __shared__ float red[256];
    red[tid] = mx;
    __syncthreads();
    for (int s = 128; s > 0; s >>= 1) {
        if (tid < s) red[tid] = fmaxf(red[tid], red[tid + s]);
        __syncthreads();
    }
    mx = red[0];
    __syncthreads();

    float sum = 0.f;
#pragma unroll
    for (int i = 0; i < 16; i++) sum += __expf(v[i] - mx);
    red[tid] = sum;
    __syncthreads();
    for (int s = 128; s > 0; s >>= 1) {
        if (tid < s) red[tid] += red[tid + s];
        __syncthreads();
    }
    if (tid == 0) { rmax[row] = mx; rinv[row] = 1.f / red[0]; }
}

// ---------------------------------------------------------------------------
#define SMEM_SZ (128*132*4)   // 67584 B >= 2 k-buffers (65536 B)

extern "C" void kernel_launch(void* const* d_in, const int* in_sizes, int n_in,
                              void* d_out, int out_size)
{
    (void)in_sizes; (void)n_in; (void)out_size;
    const float* x     = (const float*)d_in[0];
    const float* Wq    = (const float*)d_in[1];
    const float* bq    = (const float*)d_in[2];
    const float* Wk    = (const float*)d_in[3];
    const float* bk    = (const float*)d_in[4];
    const float* Wv    = (const float*)d_in[5];
    const float* bv    = (const float*)d_in[6];
    const float* Wres  = (const float*)d_in[7];
    const float* bres  = (const float*)d_in[8];
    const float* gamma = (const float*)d_in[9];

    float* out     = (float*)d_out;
    float* segmap  = out;                          // (B,N,K)
    float* featmap = out + (size_t)Bb * Nn * Kk;   // (B,N,C)

    float *pXcat, *pWcat, *pbqk, *pQcat, *pKcat, *pVt, *pS, *pO, *pRmax, *pRinv;
    cudaGetSymbolAddress((void**)&pXcat, g_Xcat);
    cudaGetSymbolAddress((void**)&pWcat, g_Wcat);
    cudaGetSymbolAddress((void**)&pbqk,  g_bqk);
    cudaGetSymbolAddress((void**)&pQcat, g_Qcat);
    cudaGetSymbolAddress((void**)&pKcat, g_Kcat);
    cudaGetSymbolAddress((void**)&pVt,   g_Vt);
    cudaGetSymbolAddress((void**)&pS,    g_S);
    cudaGetSymbolAddress((void**)&pO,    g_O);
    cudaGetSymbolAddress((void**)&pRmax, g_Rmax);
    cudaGetSymbolAddress((void**)&pRinv, g_Rinv);

    cudaFuncSetAttribute(gemm_mma,
        cudaFuncAttributeMaxDynamicSharedMemorySize, SMEM_SZ);

    // --- prep: split x / weights, zero cat-pads -----------------------------
    split_x_kernel<<<(MROWS * Cc + 255) / 256, 256>>>(x, pXcat);
    prep_w_kernel<<<(300 * 512 + 255) / 256, 256>>>(Wq, Wk, bq, bk, pWcat, pbqk);
    zero_pads_kernel<<<MROWS, 32>>>(pQcat, pKcat);

    // --- v = x @ Wv^T + bv, stored transposed (C, B*N) ----------------------
    gemm_mma<<<dim3(4, 256, 1), 256, SMEM_SZ>>>(
        x, Wv, pVt, MROWS, Cc, Cc, Cc, Cc, 0, 0, 0,
        bv, nullptr, nullptr, nullptr, (long long)MROWS,
        nullptr, nullptr, nullptr);

    // --- Q,K projections (exact 3xTF32 via cat-K), emits segmap+qcat+kcat ---
    gemm_mma<<<dim3(3, 256, 1), 256, SMEM_SZ>>>(
        pXcat, pWcat, segmap, MROWS, 300, 1536, 1536, 1536, 0, 0, 0,
        pbqk, nullptr, nullptr, nullptr, 0,
        nullptr, pQcat, pKcat);

    // --- S = Qcat @ Kcat^T per batch (Kd=480) --------------------------------
    gemm_mma<<<dim3(32, 32, Bb), 256, SMEM_SZ>>>(
        pQcat, pKcat, pS, Nn, Nn, QCW, QCW, QCW,
        (size_t)Nn * QCW, (size_t)Nn * QCW, (size_t)Nn * Nn,
        nullptr, nullptr, nullptr, nullptr, 0,
        nullptr, nullptr, nullptr);

    // --- row max / inverse softmax sum ---------------------------------------
    rowstat_kernel<<<MROWS, 256>>>(pS, pRmax, pRinv);

    // --- O = softmax(S) @ V, exp applied on the fly, rinv in epilogue --------
    gemm_mma<<<dim3(4, 32, Bb), 256, SMEM_SZ>>>(
        pS, pVt, pO, Nn, Cc, Nn, Nn, MROWS,
        (size_t)Nn * Nn, (size_t)Nn, (size_t)Nn * Cc,
        nullptr, pRinv, nullptr, nullptr, 0,
        pRmax, nullptr, nullptr);

    // --- feat_map = gamma * (O @ Wres^T + bres) + x ---------------------------
    gemm_mma<<<dim3(4, 256, 1), 256, SMEM_SZ>>>(
        pO, Wres, featmap, MROWS, Cc, Cc, Cc, Cc, 0, 0, 0,
        bres, nullptr, x, gamma, 0,
        nullptr, nullptr, nullptr);
}